// round 6
// baseline (speedup 1.0000x reference)
#include <cuda_runtime.h>

// ---------------- problem constants ----------------
#define NN      50000      // nodes
#define ET      1000000    // edges total
#define EH      500000     // edges half
#define ND      256        // node dim
#define ED      64         // edge dim
#define EK      101        // edge_in feature dim (64 + 5 + 32)

#define MU_STEP (10.0f / 31.0f)   // linspace(0,10,32) step
#define INV_SIG 3.2f              // 1 / (10/32)

// h scratch: N x 256 fp32 (51.2 MB) — static device array (no runtime alloc).
// Note: fits in B300 L2 (~126 MB), so K2's reads of g_h are mostly L2 hits.
__device__ float g_h[NN * ND];

// ---------------- f32x2 packed-FMA helpers (sm_103a FFMA2) ----------------
static __device__ __forceinline__ unsigned long long pk2(float x, float y) {
    unsigned long long r;
    asm("mov.b64 %0, {%1, %2};" : "=l"(r) : "f"(x), "f"(y));
    return r;
}
static __device__ __forceinline__ void upk2(unsigned long long p, float &x, float &y) {
    asm("mov.b64 {%0, %1}, %2;" : "=f"(x), "=f"(y) : "l"(p));
}
static __device__ __forceinline__ unsigned long long fma2(
    unsigned long long a, unsigned long long b, unsigned long long c) {
    unsigned long long d;
    asm("fma.rn.f32x2 %0, %1, %2, %3;" : "=l"(d) : "l"(a), "l"(b), "l"(c));
    return d;
}

static __device__ __forceinline__ float siluf(float x) {
    return x / (1.0f + __expf(-x));
}

// ============================================================================
// K1: node features + first GEMM  ->  g_h[n][256] = f[n][64] @ Wcat + bsum
//   f = [rbf32 | dv16 | a16], Wcat = [W_x; W_v; W_a], bsum = b_x+b_v+b_a
//   64 nodes / block, 256 threads, 8x8 microtile on f32x2.
// ============================================================================
#define K1_NT 64
#define K1_AP 68   // padded row stride for f^T tile (68 mod 32 = 4 -> 2-way worst)

__global__ void __launch_bounds__(256)
k1_node_h(const float* __restrict__ x_t,  const float* __restrict__ v_t,
          const float* __restrict__ dst_x, const float* __restrict__ dst_v,
          const float* __restrict__ dst_a,
          const float* __restrict__ W_x, const float* __restrict__ b_x,
          const float* __restrict__ W_v, const float* __restrict__ b_v,
          const float* __restrict__ W_a, const float* __restrict__ b_a)
{
    extern __shared__ float sm1[];
    float* Bs   = sm1;                     // [64][256] Wcat
    float* As   = Bs + 64 * 256;           // [64][K1_AP] f^T  (As[k][m])
    float* bsum = As + 64 * K1_AP;         // [256]

    const int t  = threadIdx.x;
    const int nb = blockIdx.x * K1_NT;

    // stage Wcat (coalesced: consecutive t -> consecutive cols)
    for (int i = t; i < 64 * 256; i += 256) {
        int k = i >> 8, c = i & 255;
        float w;
        if (k < 32)      w = W_x[k * 256 + c];
        else if (k < 48) w = W_v[(k - 32) * 256 + c];
        else             w = W_a[(k - 48) * 256 + c];
        Bs[i] = w;
    }
    bsum[t] = b_x[t] + b_v[t] + b_a[t];

    // per-node features (threads 0..63)
    if (t < K1_NT) {
        int n = nb + t;
        if (n < NN) {
            float dx0 = x_t[3*n+0] - dst_x[3*n+0];
            float dx1 = x_t[3*n+1] - dst_x[3*n+1];
            float dx2 = x_t[3*n+2] - dst_x[3*n+2];
            float d = sqrtf(fmaxf(dx0*dx0 + dx1*dx1 + dx2*dx2, 1e-8f));
            #pragma unroll
            for (int k = 0; k < 32; k++) {
                float z = (d - (float)k * MU_STEP) * INV_SIG;
                As[k * K1_AP + t] = __expf(-z * z);
            }
            float vt[12], dv[12];
            #pragma unroll
            for (int i = 0; i < 12; i++) { vt[i] = v_t[12*n + i]; dv[i] = dst_v[12*n + i]; }
            #pragma unroll
            for (int c1 = 0; c1 < 4; c1++) {
                #pragma unroll
                for (int c2 = 0; c2 < 4; c2++) {
                    float a0 = vt[3*c1+0] - dv[3*c2+0];
                    float a1 = vt[3*c1+1] - dv[3*c2+1];
                    float a2 = vt[3*c1+2] - dv[3*c2+2];
                    As[(32 + c1*4 + c2) * K1_AP + t] =
                        sqrtf(fmaxf(a0*a0 + a1*a1 + a2*a2, 1e-8f));
                }
            }
            #pragma unroll
            for (int k = 0; k < 16; k++)
                As[(48 + k) * K1_AP + t] = dst_a[16*n + k];
        } else {
            #pragma unroll
            for (int k = 0; k < 64; k++) As[k * K1_AP + t] = 0.0f;
        }
    }
    __syncthreads();

    // GEMM 64x256, K=64.  warp-uniform A (broadcast), vectorized B.
    const int tm = t >> 5, tn = t & 31;     // tm: 8 node groups, tn: 32 col groups
    const int m0 = tm * 8, n0 = tn * 8;

    unsigned long long acc[8][4];
    #pragma unroll
    for (int i = 0; i < 8; i++)
        #pragma unroll
        for (int j = 0; j < 4; j++) acc[i][j] = 0ULL;

    #pragma unroll 8
    for (int k = 0; k < 64; k++) {
        float4 a0 = *(const float4*)&As[k * K1_AP + m0];
        float4 a1 = *(const float4*)&As[k * K1_AP + m0 + 4];
        float4 b0 = *(const float4*)&Bs[k * 256 + n0];
        float4 b1 = *(const float4*)&Bs[k * 256 + n0 + 4];
        float am[8] = {a0.x, a0.y, a0.z, a0.w, a1.x, a1.y, a1.z, a1.w};
        unsigned long long bb[4] = {pk2(b0.x, b0.y), pk2(b0.z, b0.w),
                                    pk2(b1.x, b1.y), pk2(b1.z, b1.w)};
        #pragma unroll
        for (int i = 0; i < 8; i++) {
            unsigned long long aa = pk2(am[i], am[i]);
            #pragma unroll
            for (int j = 0; j < 4; j++) acc[i][j] = fma2(aa, bb[j], acc[i][j]);
        }
    }

    #pragma unroll
    for (int i = 0; i < 8; i++) {
        int n = nb + m0 + i;
        if (n < NN) {
            float v[8];
            #pragma unroll
            for (int j = 0; j < 4; j++) upk2(acc[i][j], v[2*j], v[2*j+1]);
            float4 o0 = make_float4(v[0] + bsum[n0+0], v[1] + bsum[n0+1],
                                    v[2] + bsum[n0+2], v[3] + bsum[n0+3]);
            float4 o1 = make_float4(v[4] + bsum[n0+4], v[5] + bsum[n0+5],
                                    v[6] + bsum[n0+6], v[7] + bsum[n0+7]);
            *(float4*)&g_h[n * 256 + n0]     = o0;
            *(float4*)&g_h[n * 256 + n0 + 4] = o1;
        }
    }
}

// ============================================================================
// K2: node_out = s_t + silu(g_h @ W_n + b_n)
//   BM=128, BN=128, BK=16, 256 threads, 8x8 microtile on f32x2.
//   Double-buffered smem: LDG (regs) -> compute(buf) -> STS(buf^1) -> 1 barrier.
// ============================================================================
#define K2_BM 128
#define K2_BN 128
#define K2_BK 16
#define K2_AP 132   // 132 mod 32 = 4 -> transpose STS 2-way (136 was 4-way)

__global__ void __launch_bounds__(256)
k2_node_out(const float* __restrict__ s_t, const float* __restrict__ W_n,
            const float* __restrict__ b_n, float* __restrict__ out)
{
    __shared__ float As[2][K2_BK][K2_AP];   // h^T tile: As[buf][k][m]
    __shared__ float Bs[2][K2_BK][K2_BN];   // W_n tile: Bs[buf][k][n]
    __shared__ float bn_sh[K2_BN];

    const int t  = threadIdx.x;
    const int mB = blockIdx.x * K2_BM;
    const int nB = blockIdx.y * K2_BN;

    if (t < K2_BN) bn_sh[t] = b_n[nB + t];

    // ---- load-index precompute (fixed per thread) ----
    const int a_m  = t >> 2;            // 0..63 (+64 for p=1)
    const int a_k4 = (t & 3) * 4;       // 0,4,8,12
    const int b_k  = t >> 5;            // 0..7 (+8 for p=1)
    const int b_n4 = (t & 31) * 4;      // 0..124

    const int gm0 = mB + a_m;
    const int gm1 = mB + a_m + 64;

    // ---- prologue: fetch tile 0 into regs ----
    float4 aR[2], bR[2];
    {
        aR[0] = (gm0 < NN) ? *(const float4*)&g_h[gm0 * 256 + a_k4]
                           : make_float4(0.f, 0.f, 0.f, 0.f);
        aR[1] = (gm1 < NN) ? *(const float4*)&g_h[gm1 * 256 + a_k4]
                           : make_float4(0.f, 0.f, 0.f, 0.f);
        bR[0] = *(const float4*)&W_n[b_k * 256 + nB + b_n4];
        bR[1] = *(const float4*)&W_n[(b_k + 8) * 256 + nB + b_n4];
    }
    // store tile 0 into buf 0
    As[0][a_k4+0][a_m]      = aR[0].x; As[0][a_k4+1][a_m]      = aR[0].y;
    As[0][a_k4+2][a_m]      = aR[0].z; As[0][a_k4+3][a_m]      = aR[0].w;
    As[0][a_k4+0][a_m+64]   = aR[1].x; As[0][a_k4+1][a_m+64]   = aR[1].y;
    As[0][a_k4+2][a_m+64]   = aR[1].z; As[0][a_k4+3][a_m+64]   = aR[1].w;
    *(float4*)&Bs[0][b_k][b_n4]     = bR[0];
    *(float4*)&Bs[0][b_k+8][b_n4]   = bR[1];
    __syncthreads();

    const int tm = t >> 4, tn = t & 15;
    const int m0 = tm * 8, n0 = tn * 8;

    unsigned long long acc[8][4];
    #pragma unroll
    for (int i = 0; i < 8; i++)
        #pragma unroll
        for (int j = 0; j < 4; j++) acc[i][j] = 0ULL;

    int buf = 0;
    for (int kt = 0; kt < 256; kt += K2_BK) {
        const bool has_next = (kt + K2_BK) < 256;
        // prefetch next tile into registers (overlaps with compute below)
        if (has_next) {
            int kn = kt + K2_BK;
            aR[0] = (gm0 < NN) ? *(const float4*)&g_h[gm0 * 256 + kn + a_k4]
                               : make_float4(0.f, 0.f, 0.f, 0.f);
            aR[1] = (gm1 < NN) ? *(const float4*)&g_h[gm1 * 256 + kn + a_k4]
                               : make_float4(0.f, 0.f, 0.f, 0.f);
            bR[0] = *(const float4*)&W_n[(kn + b_k) * 256 + nB + b_n4];
            bR[1] = *(const float4*)&W_n[(kn + b_k + 8) * 256 + nB + b_n4];
        }

        // compute on current buffer
        #pragma unroll
        for (int k = 0; k < K2_BK; k++) {
            float4 a0 = *(const float4*)&As[buf][k][m0];
            float4 a1 = *(const float4*)&As[buf][k][m0 + 4];
            float4 b0 = *(const float4*)&Bs[buf][k][n0];
            float4 b1 = *(const float4*)&Bs[buf][k][n0 + 4];
            float am[8] = {a0.x, a0.y, a0.z, a0.w, a1.x, a1.y, a1.z, a1.w};
            unsigned long long bb[4] = {pk2(b0.x, b0.y), pk2(b0.z, b0.w),
                                        pk2(b1.x, b1.y), pk2(b1.z, b1.w)};
            #pragma unroll
            for (int i = 0; i < 8; i++) {
                unsigned long long aa = pk2(am[i], am[i]);
                #pragma unroll
                for (int j = 0; j < 4; j++) acc[i][j] = fma2(aa, bb[j], acc[i][j]);
            }
        }

        // store prefetched tile into the other buffer, single barrier
        if (has_next) {
            int nb2 = buf ^ 1;
            As[nb2][a_k4+0][a_m]    = aR[0].x; As[nb2][a_k4+1][a_m]    = aR[0].y;
            As[nb2][a_k4+2][a_m]    = aR[0].z; As[nb2][a_k4+3][a_m]    = aR[0].w;
            As[nb2][a_k4+0][a_m+64] = aR[1].x; As[nb2][a_k4+1][a_m+64] = aR[1].y;
            As[nb2][a_k4+2][a_m+64] = aR[1].z; As[nb2][a_k4+3][a_m+64] = aR[1].w;
            *(float4*)&Bs[nb2][b_k][b_n4]   = bR[0];
            *(float4*)&Bs[nb2][b_k+8][b_n4] = bR[1];
            __syncthreads();
            buf = nb2;
        }
    }

    #pragma unroll
    for (int i = 0; i < 8; i++) {
        int gm = mB + m0 + i;
        if (gm < NN) {
            int col = nB + n0;
            float v[8];
            #pragma unroll
            for (int j = 0; j < 4; j++) upk2(acc[i][j], v[2*j], v[2*j+1]);
            float4 s0 = *(const float4*)&s_t[gm * 256 + col];
            float4 s1 = *(const float4*)&s_t[gm * 256 + col + 4];
            float4 o0 = make_float4(s0.x + siluf(v[0] + bn_sh[n0+0]),
                                    s0.y + siluf(v[1] + bn_sh[n0+1]),
                                    s0.z + siluf(v[2] + bn_sh[n0+2]),
                                    s0.w + siluf(v[3] + bn_sh[n0+3]));
            float4 o1 = make_float4(s1.x + siluf(v[4] + bn_sh[n0+4]),
                                    s1.y + siluf(v[5] + bn_sh[n0+5]),
                                    s1.z + siluf(v[6] + bn_sh[n0+6]),
                                    s1.w + siluf(v[7] + bn_sh[n0+7]));
            *(float4*)&out[gm * 256 + col]     = o0;
            *(float4*)&out[gm * 256 + col + 4] = o1;
        }
    }
}

// ============================================================================
// K3: edge residual. 128 edges / block.
//   edge_in (101) staged TRANSPOSED in smem -> vectorized A loads.
//   out[e] = out[e + EH] = silu(edge_in @ W_e + b_e)
// ============================================================================
#define K3_TE 128
#define K3_EP 132

__global__ void __launch_bounds__(256)
k3_edge(const float* __restrict__ x_t,  const float* __restrict__ dst_x,
        const float* __restrict__ e_t,  const float* __restrict__ dst_e,
        const int* __restrict__ esrc,   const int* __restrict__ edst,
        const float* __restrict__ W_e,  const float* __restrict__ b_e,
        float* __restrict__ out)   // already offset to edge region
{
    extern __shared__ float sm3[];
    float* in_sh = sm3;                       // [101][K3_EP]  in_sh[k][e]
    float* W_sh  = in_sh + EK * K3_EP;        // [101][64]
    float* d1_sh = W_sh + EK * 64;            // [128]
    float* dt_sh = d1_sh + K3_TE;             // [128]

    const int t  = threadIdx.x;
    const int eb = blockIdx.x * K3_TE;
    const int nvalid = min(K3_TE, EH - eb);

    // stage W_e
    for (int i = t; i < EK * 64; i += 256) W_sh[i] = W_e[i];

    // stage e_t rows 0..63 (read coalesced float4, write transposed)
    for (int i = t; i < K3_TE * 16; i += 256) {
        int e = i >> 4, k4 = (i & 15) * 4;
        float4 v = (e < nvalid) ? *(const float4*)&e_t[(eb + e) * 64 + k4]
                                : make_float4(0.f, 0.f, 0.f, 0.f);
        in_sh[(k4+0) * K3_EP + e] = v.x;
        in_sh[(k4+1) * K3_EP + e] = v.y;
        in_sh[(k4+2) * K3_EP + e] = v.z;
        in_sh[(k4+3) * K3_EP + e] = v.w;
    }
    // stage dst_e rows 64..68 (reads fully coalesced: (eb+e)*5+k == eb*5+i)
    for (int i = t; i < K3_TE * 5; i += 256) {
        int e = i / 5, k = i % 5;
        in_sh[(64 + k) * K3_EP + e] = (e < nvalid) ? dst_e[(eb + e) * 5 + k] : 0.0f;
    }
    // edge distances (x_t / dst_x are L2-resident gathers)
    if (t < K3_TE) {
        if (t < nvalid) {
            int s = esrc[eb + t], d = edst[eb + t];
            float a0 = x_t[3*s+0] - x_t[3*d+0];
            float a1 = x_t[3*s+1] - x_t[3*d+1];
            float a2 = x_t[3*s+2] - x_t[3*d+2];
            dt_sh[t] = sqrtf(fmaxf(a0*a0 + a1*a1 + a2*a2, 1e-8f));
            float c0 = dst_x[3*s+0] - dst_x[3*d+0];
            float c1 = dst_x[3*s+1] - dst_x[3*d+1];
            float c2 = dst_x[3*s+2] - dst_x[3*d+2];
            d1_sh[t] = sqrtf(fmaxf(c0*c0 + c1*c1 + c2*c2, 1e-8f));
        } else {
            dt_sh[t] = 0.0f; d1_sh[t] = 0.0f;
        }
    }
    __syncthreads();

    // rbf difference rows 69..100 (exps spread across all 256 threads)
    for (int i = t; i < K3_TE * 32; i += 256) {
        int e = i & (K3_TE - 1), k = i >> 7;
        float mu = (float)k * MU_STEP;
        float z1 = (d1_sh[e] - mu) * INV_SIG;
        float z0 = (dt_sh[e] - mu) * INV_SIG;
        in_sh[(69 + k) * K3_EP + e] = __expf(-z1*z1) - __expf(-z0*z0);
    }
    __syncthreads();

    // GEMM 128 x 64, K=101.  8 edges x 4 cols per thread.
    const int tn = t & 15, te = t >> 4;
    const int e0 = te * 8, n0 = tn * 4;

    unsigned long long acc[8][2];
    #pragma unroll
    for (int i = 0; i < 8; i++) { acc[i][0] = 0ULL; acc[i][1] = 0ULL; }

    #pragma unroll 4
    for (int k = 0; k < EK; k++) {
        float4 a0 = *(const float4*)&in_sh[k * K3_EP + e0];
        float4 a1 = *(const float4*)&in_sh[k * K3_EP + e0 + 4];
        float4 b  = *(const float4*)&W_sh[k * 64 + n0];
        float am[8] = {a0.x, a0.y, a0.z, a0.w, a1.x, a1.y, a1.z, a1.w};
        unsigned long long b01 = pk2(b.x, b.y), b23 = pk2(b.z, b.w);
        #pragma unroll
        for (int i = 0; i < 8; i++) {
            unsigned long long aa = pk2(am[i], am[i]);
            acc[i][0] = fma2(aa, b01, acc[i][0]);
            acc[i][1] = fma2(aa, b23, acc[i][1]);
        }
    }

    float be0 = b_e[n0+0], be1 = b_e[n0+1], be2 = b_e[n0+2], be3 = b_e[n0+3];
    #pragma unroll
    for (int i = 0; i < 8; i++) {
        int e = e0 + i;
        if (e < nvalid) {
            float v0, v1, v2, v3;
            upk2(acc[i][0], v0, v1);
            upk2(acc[i][1], v2, v3);
            float4 o = make_float4(siluf(v0 + be0), siluf(v1 + be1),
                                   siluf(v2 + be2), siluf(v3 + be3));
            int base = (eb + e) * 64 + n0;
            *(float4*)&out[base]            = o;   // upper edge
            *(float4*)&out[base + EH * 64]  = o;   // mirrored lower edge
        }
    }
}

// ============================================================================
// launch
// ============================================================================
extern "C" void kernel_launch(void* const* d_in, const int* in_sizes, int n_in,
                              void* d_out, int out_size)
{
    const float *s_t  = (const float*)d_in[0];
    const float *x_t  = (const float*)d_in[1];
    const float *v_t  = (const float*)d_in[2];
    const float *e_t  = (const float*)d_in[3];
    const float *dst_x = (const float*)d_in[4];
    const float *dst_v = (const float*)d_in[5];
    const float *dst_a = (const float*)d_in[6];
    const float *dst_e = (const float*)d_in[7];
    const float *W_x, *b_x, *W_v, *b_v, *W_a, *b_a, *W_n, *b_n, *W_e, *b_e;
    const int *esrc, *edst;

    if (in_sizes[8] == ET) {
        // setup_inputs dict order: edge_src/edge_dst at 8/9
        esrc = (const int*)d_in[8];   edst = (const int*)d_in[9];
        W_x = (const float*)d_in[10]; b_x = (const float*)d_in[11];
        W_v = (const float*)d_in[12]; b_v = (const float*)d_in[13];
        W_a = (const float*)d_in[14]; b_a = (const float*)d_in[15];
        W_n = (const float*)d_in[16]; b_n = (const float*)d_in[17];
        W_e = (const float*)d_in[18]; b_e = (const float*)d_in[19];
    } else {
        // reference() signature order: weights at 8..17, indices at 18/19
        W_x = (const float*)d_in[8];  b_x = (const float*)d_in[9];
        W_v = (const float*)d_in[10]; b_v = (const float*)d_in[11];
        W_a = (const float*)d_in[12]; b_a = (const float*)d_in[13];
        W_n = (const float*)d_in[14]; b_n = (const float*)d_in[15];
        W_e = (const float*)d_in[16]; b_e = (const float*)d_in[17];
        esrc = (const int*)d_in[18];  edst = (const int*)d_in[19];
    }

    float* out = (float*)d_out;

    const int k1_smem = (64 * 256 + 64 * K1_AP + 256) * (int)sizeof(float);      // ~84 KB
    const int k3_smem = (EK * K3_EP + EK * 64 + 2 * K3_TE) * (int)sizeof(float); // ~80 KB
    cudaFuncSetAttribute(k1_node_h, cudaFuncAttributeMaxDynamicSharedMemorySize, k1_smem);
    cudaFuncSetAttribute(k3_edge,  cudaFuncAttributeMaxDynamicSharedMemorySize, k3_smem);

    k1_node_h<<<(NN + K1_NT - 1) / K1_NT, 256, k1_smem>>>(
        x_t, v_t, dst_x, dst_v, dst_a, W_x, b_x, W_v, b_v, W_a, b_a);

    k2_node_out<<<dim3((NN + K2_BM - 1) / K2_BM, ND / K2_BN), 256>>>(
        s_t, W_n, b_n, out);

    k3_edge<<<(EH + K3_TE - 1) / K3_TE, 256, k3_smem>>>(
        x_t, dst_x, e_t, dst_e, esrc, edst, W_e, b_e, out + NN * ND);
}

// round 7
// speedup vs baseline: 1.2391x; 1.2391x over previous
#include <cuda_runtime.h>

// ---------------- problem constants ----------------
#define NN      50000      // nodes
#define ET      1000000    // edges total
#define EH      500000     // edges half
#define ND      256        // node dim
#define ED      64         // edge dim
#define EK      101        // edge_in feature dim (64 + 5 + 32)

#define MU_STEP (10.0f / 31.0f)   // linspace(0,10,32) step
#define INV_SIG 3.2f              // 1 / (10/32)

// h scratch: N x 256 fp32 (51.2 MB) — static device array (L2-resident on B300)
__device__ float g_h[NN * ND];

// ---------------- f32x2 packed-FMA helpers (sm_103a FFMA2) ----------------
static __device__ __forceinline__ unsigned long long pk2(float x, float y) {
    unsigned long long r;
    asm("mov.b64 %0, {%1, %2};" : "=l"(r) : "f"(x), "f"(y));
    return r;
}
static __device__ __forceinline__ void upk2(unsigned long long p, float &x, float &y) {
    asm("mov.b64 {%0, %1}, %2;" : "=f"(x), "=f"(y) : "l"(p));
}
static __device__ __forceinline__ unsigned long long fma2(
    unsigned long long a, unsigned long long b, unsigned long long c) {
    unsigned long long d;
    asm("fma.rn.f32x2 %0, %1, %2, %3;" : "=l"(d) : "l"(a), "l"(b), "l"(c));
    return d;
}

static __device__ __forceinline__ float siluf(float x) {
    return x / (1.0f + __expf(-x));
}

// ============================================================================
// K1: node features + first GEMM  ->  g_h[n][256] = f[n][64] @ Wcat + bsum
//   B-loads conflict-free: each thread covers cols {tn*4..+3} and {128+tn*4..+3}
//   Features computed by 4 threads per node. Wcat staged as float4.
// ============================================================================
#define K1_NT 64
#define K1_AP 68

__global__ void __launch_bounds__(256)
k1_node_h(const float* __restrict__ x_t,  const float* __restrict__ v_t,
          const float* __restrict__ dst_x, const float* __restrict__ dst_v,
          const float* __restrict__ dst_a,
          const float* __restrict__ W_x, const float* __restrict__ b_x,
          const float* __restrict__ W_v, const float* __restrict__ b_v,
          const float* __restrict__ W_a, const float* __restrict__ b_a)
{
    extern __shared__ float sm1[];
    float* Bs   = sm1;                     // [64][256] Wcat
    float* As   = Bs + 64 * 256;           // [64][K1_AP] f^T
    float* bsum = As + 64 * K1_AP;         // [256]

    const int t  = threadIdx.x;
    const int nb = blockIdx.x * K1_NT;

    // stage Wcat as float4 (16 iterations, coalesced)
    for (int i = t; i < 64 * 64; i += 256) {
        int k = i >> 6, c4 = (i & 63) * 4;
        float4 w;
        if (k < 32)      w = *(const float4*)&W_x[k * 256 + c4];
        else if (k < 48) w = *(const float4*)&W_v[(k - 32) * 256 + c4];
        else             w = *(const float4*)&W_a[(k - 48) * 256 + c4];
        *(float4*)&Bs[k * 256 + c4] = w;
    }
    bsum[t] = b_x[t] + b_v[t] + b_a[t];

    // features: 4 threads per node (part = t>>6 handles 8 RBF + 4 dv + 4 a rows)
    {
        const int node = t & 63, part = t >> 6;
        const int n = nb + node;
        if (n < NN) {
            float dx0 = x_t[3*n+0] - dst_x[3*n+0];
            float dx1 = x_t[3*n+1] - dst_x[3*n+1];
            float dx2 = x_t[3*n+2] - dst_x[3*n+2];
            float d = sqrtf(fmaxf(dx0*dx0 + dx1*dx1 + dx2*dx2, 1e-8f));
            #pragma unroll
            for (int kk = 0; kk < 8; kk++) {
                int k = part * 8 + kk;
                float z = (d - (float)k * MU_STEP) * INV_SIG;
                As[k * K1_AP + node] = __expf(-z * z);
            }
            float vt0 = v_t[12*n + 3*part + 0];
            float vt1 = v_t[12*n + 3*part + 1];
            float vt2 = v_t[12*n + 3*part + 2];
            #pragma unroll
            for (int c2 = 0; c2 < 4; c2++) {
                float a0 = vt0 - dst_v[12*n + 3*c2 + 0];
                float a1 = vt1 - dst_v[12*n + 3*c2 + 1];
                float a2 = vt2 - dst_v[12*n + 3*c2 + 2];
                As[(32 + part*4 + c2) * K1_AP + node] =
                    sqrtf(fmaxf(a0*a0 + a1*a1 + a2*a2, 1e-8f));
            }
            float4 av = *(const float4*)&dst_a[16*n + part*4];
            As[(48 + part*4 + 0) * K1_AP + node] = av.x;
            As[(48 + part*4 + 1) * K1_AP + node] = av.y;
            As[(48 + part*4 + 2) * K1_AP + node] = av.z;
            As[(48 + part*4 + 3) * K1_AP + node] = av.w;
        } else {
            #pragma unroll
            for (int kk = 0; kk < 16; kk++)
                As[(part * 16 + kk) * K1_AP + node] = 0.0f;
        }
    }
    __syncthreads();

    // GEMM 64x256, K=64.  A warp-broadcast; B contiguous per warp (no conflicts).
    const int tm = t >> 5, tn = t & 31;
    const int m0 = tm * 8;
    const int nA = tn * 4, nB2 = 128 + tn * 4;

    unsigned long long acc[8][4];
    #pragma unroll
    for (int i = 0; i < 8; i++)
        #pragma unroll
        for (int j = 0; j < 4; j++) acc[i][j] = 0ULL;

    #pragma unroll 8
    for (int k = 0; k < 64; k++) {
        float4 a0 = *(const float4*)&As[k * K1_AP + m0];
        float4 a1 = *(const float4*)&As[k * K1_AP + m0 + 4];
        float4 b0 = *(const float4*)&Bs[k * 256 + nA];
        float4 b1 = *(const float4*)&Bs[k * 256 + nB2];
        float am[8] = {a0.x, a0.y, a0.z, a0.w, a1.x, a1.y, a1.z, a1.w};
        unsigned long long bb[4] = {pk2(b0.x, b0.y), pk2(b0.z, b0.w),
                                    pk2(b1.x, b1.y), pk2(b1.z, b1.w)};
        #pragma unroll
        for (int i = 0; i < 8; i++) {
            unsigned long long aa = pk2(am[i], am[i]);
            #pragma unroll
            for (int j = 0; j < 4; j++) acc[i][j] = fma2(aa, bb[j], acc[i][j]);
        }
    }

    #pragma unroll
    for (int i = 0; i < 8; i++) {
        int n = nb + m0 + i;
        if (n < NN) {
            float v[8];
            #pragma unroll
            for (int j = 0; j < 4; j++) upk2(acc[i][j], v[2*j], v[2*j+1]);
            float4 o0 = make_float4(v[0] + bsum[nA+0], v[1] + bsum[nA+1],
                                    v[2] + bsum[nA+2], v[3] + bsum[nA+3]);
            float4 o1 = make_float4(v[4] + bsum[nB2+0], v[5] + bsum[nB2+1],
                                    v[6] + bsum[nB2+2], v[7] + bsum[nB2+3]);
            *(float4*)&g_h[n * 256 + nA]  = o0;
            *(float4*)&g_h[n * 256 + nB2] = o1;
        }
    }
}

// ============================================================================
// K2: node_out = s_t + silu(g_h @ W_n + b_n)
//   Double-buffered; B-loads conflict-free via split cols {tn*4, 64+tn*4}.
// ============================================================================
#define K2_BM 128
#define K2_BN 128
#define K2_BK 16
#define K2_AP 132

__global__ void __launch_bounds__(256)
k2_node_out(const float* __restrict__ s_t, const float* __restrict__ W_n,
            const float* __restrict__ b_n, float* __restrict__ out)
{
    __shared__ float As[2][K2_BK][K2_AP];
    __shared__ float Bs[2][K2_BK][K2_BN];
    __shared__ float bn_sh[K2_BN];

    const int t  = threadIdx.x;
    const int mB = blockIdx.x * K2_BM;
    const int nB = blockIdx.y * K2_BN;

    if (t < K2_BN) bn_sh[t] = b_n[nB + t];

    const int a_m  = t >> 2;
    const int a_k4 = (t & 3) * 4;
    const int b_k  = t >> 5;
    const int b_n4 = (t & 31) * 4;

    const int gm0 = mB + a_m;
    const int gm1 = mB + a_m + 64;

    float4 aR[2], bR[2];
    {
        aR[0] = (gm0 < NN) ? *(const float4*)&g_h[gm0 * 256 + a_k4]
                           : make_float4(0.f, 0.f, 0.f, 0.f);
        aR[1] = (gm1 < NN) ? *(const float4*)&g_h[gm1 * 256 + a_k4]
                           : make_float4(0.f, 0.f, 0.f, 0.f);
        bR[0] = *(const float4*)&W_n[b_k * 256 + nB + b_n4];
        bR[1] = *(const float4*)&W_n[(b_k + 8) * 256 + nB + b_n4];
    }
    As[0][a_k4+0][a_m]      = aR[0].x; As[0][a_k4+1][a_m]      = aR[0].y;
    As[0][a_k4+2][a_m]      = aR[0].z; As[0][a_k4+3][a_m]      = aR[0].w;
    As[0][a_k4+0][a_m+64]   = aR[1].x; As[0][a_k4+1][a_m+64]   = aR[1].y;
    As[0][a_k4+2][a_m+64]   = aR[1].z; As[0][a_k4+3][a_m+64]   = aR[1].w;
    *(float4*)&Bs[0][b_k][b_n4]     = bR[0];
    *(float4*)&Bs[0][b_k+8][b_n4]   = bR[1];
    __syncthreads();

    const int tm = t >> 4, tn = t & 15;
    const int m0 = tm * 8;
    const int nA = tn * 4, nB2 = 64 + tn * 4;   // split column groups

    unsigned long long acc[8][4];
    #pragma unroll
    for (int i = 0; i < 8; i++)
        #pragma unroll
        for (int j = 0; j < 4; j++) acc[i][j] = 0ULL;

    int buf = 0;
    for (int kt = 0; kt < 256; kt += K2_BK) {
        const bool has_next = (kt + K2_BK) < 256;
        if (has_next) {
            int kn = kt + K2_BK;
            aR[0] = (gm0 < NN) ? *(const float4*)&g_h[gm0 * 256 + kn + a_k4]
                               : make_float4(0.f, 0.f, 0.f, 0.f);
            aR[1] = (gm1 < NN) ? *(const float4*)&g_h[gm1 * 256 + kn + a_k4]
                               : make_float4(0.f, 0.f, 0.f, 0.f);
            bR[0] = *(const float4*)&W_n[(kn + b_k) * 256 + nB + b_n4];
            bR[1] = *(const float4*)&W_n[(kn + b_k + 8) * 256 + nB + b_n4];
        }

        #pragma unroll
        for (int k = 0; k < K2_BK; k++) {
            float4 a0 = *(const float4*)&As[buf][k][m0];
            float4 a1 = *(const float4*)&As[buf][k][m0 + 4];
            float4 b0 = *(const float4*)&Bs[buf][k][nA];
            float4 b1 = *(const float4*)&Bs[buf][k][nB2];
            float am[8] = {a0.x, a0.y, a0.z, a0.w, a1.x, a1.y, a1.z, a1.w};
            unsigned long long bb[4] = {pk2(b0.x, b0.y), pk2(b0.z, b0.w),
                                        pk2(b1.x, b1.y), pk2(b1.z, b1.w)};
            #pragma unroll
            for (int i = 0; i < 8; i++) {
                unsigned long long aa = pk2(am[i], am[i]);
                #pragma unroll
                for (int j = 0; j < 4; j++) acc[i][j] = fma2(aa, bb[j], acc[i][j]);
            }
        }

        if (has_next) {
            int nb2 = buf ^ 1;
            As[nb2][a_k4+0][a_m]    = aR[0].x; As[nb2][a_k4+1][a_m]    = aR[0].y;
            As[nb2][a_k4+2][a_m]    = aR[0].z; As[nb2][a_k4+3][a_m]    = aR[0].w;
            As[nb2][a_k4+0][a_m+64] = aR[1].x; As[nb2][a_k4+1][a_m+64] = aR[1].y;
            As[nb2][a_k4+2][a_m+64] = aR[1].z; As[nb2][a_k4+3][a_m+64] = aR[1].w;
            *(float4*)&Bs[nb2][b_k][b_n4]   = bR[0];
            *(float4*)&Bs[nb2][b_k+8][b_n4] = bR[1];
            __syncthreads();
            buf = nb2;
        }
    }

    #pragma unroll
    for (int i = 0; i < 8; i++) {
        int gm = mB + m0 + i;
        if (gm < NN) {
            float v[8];
            #pragma unroll
            for (int j = 0; j < 4; j++) upk2(acc[i][j], v[2*j], v[2*j+1]);
            int colA = nB + nA, colB = nB + nB2;
            float4 s0 = *(const float4*)&s_t[gm * 256 + colA];
            float4 s1 = *(const float4*)&s_t[gm * 256 + colB];
            float4 o0 = make_float4(s0.x + siluf(v[0] + bn_sh[nA+0]),
                                    s0.y + siluf(v[1] + bn_sh[nA+1]),
                                    s0.z + siluf(v[2] + bn_sh[nA+2]),
                                    s0.w + siluf(v[3] + bn_sh[nA+3]));
            float4 o1 = make_float4(s1.x + siluf(v[4] + bn_sh[nB2+0]),
                                    s1.y + siluf(v[5] + bn_sh[nB2+1]),
                                    s1.z + siluf(v[6] + bn_sh[nB2+2]),
                                    s1.w + siluf(v[7] + bn_sh[nB2+3]));
            *(float4*)&out[gm * 256 + colA] = o0;
            *(float4*)&out[gm * 256 + colB] = o1;
        }
    }
}

// ============================================================================
// K3: edge residual. 128 edges / block.
//   A tile ROW-MAJOR in_sh[e][104] (all staging stores contiguous, GEMM a-loads
//   warp-broadcast). out[e] = out[e+EH] = silu(edge_in @ W_e + b_e)
// ============================================================================
#define K3_TE 128
#define K3_KP 104   // padded row stride for 101 features

__global__ void __launch_bounds__(256)
k3_edge(const float* __restrict__ x_t,  const float* __restrict__ dst_x,
        const float* __restrict__ e_t,  const float* __restrict__ dst_e,
        const int* __restrict__ esrc,   const int* __restrict__ edst,
        const float* __restrict__ W_e,  const float* __restrict__ b_e,
        float* __restrict__ out)
{
    extern __shared__ float sm3[];
    float* in_sh = sm3;                       // [128][K3_KP] row-major
    float* W_sh  = in_sh + K3_TE * K3_KP;     // [101][64]
    float* d1_sh = W_sh + EK * 64;            // [128]
    float* dt_sh = d1_sh + K3_TE;             // [128]

    const int t  = threadIdx.x;
    const int eb = blockIdx.x * K3_TE;
    const int nvalid = min(K3_TE, EH - eb);

    // stage W_e (float4, contiguous)
    for (int i = t; i < (EK * 64) / 4; i += 256)
        *(float4*)&W_sh[i * 4] = *(const float4*)&W_e[i * 4];

    // stage e_t rows (features 0..63): contiguous float4 stores, no conflicts
    for (int i = t; i < K3_TE * 16; i += 256) {
        int e = i >> 4, k4 = (i & 15) * 4;
        float4 v = (e < nvalid) ? *(const float4*)&e_t[(eb + e) * 64 + k4]
                                : make_float4(0.f, 0.f, 0.f, 0.f);
        *(float4*)&in_sh[e * K3_KP + k4] = v;
    }
    // dst_e (features 64..68)
    for (int i = t; i < K3_TE * 5; i += 256) {
        int e = i / 5, k = i % 5;
        in_sh[e * K3_KP + 64 + k] = (e < nvalid) ? dst_e[(eb + e) * 5 + k] : 0.0f;
    }
    // edge distances
    if (t < K3_TE) {
        if (t < nvalid) {
            int s = esrc[eb + t], d = edst[eb + t];
            float a0 = x_t[3*s+0] - x_t[3*d+0];
            float a1 = x_t[3*s+1] - x_t[3*d+1];
            float a2 = x_t[3*s+2] - x_t[3*d+2];
            dt_sh[t] = sqrtf(fmaxf(a0*a0 + a1*a1 + a2*a2, 1e-8f));
            float c0 = dst_x[3*s+0] - dst_x[3*d+0];
            float c1 = dst_x[3*s+1] - dst_x[3*d+1];
            float c2 = dst_x[3*s+2] - dst_x[3*d+2];
            d1_sh[t] = sqrtf(fmaxf(c0*c0 + c1*c1 + c2*c2, 1e-8f));
        } else {
            dt_sh[t] = 0.0f; d1_sh[t] = 0.0f;
        }
    }
    __syncthreads();

    // rbf difference (features 69..100): lane = rbf index k -> contiguous STS
    {
        const int k = t & 31;
        const float mu = (float)k * MU_STEP;
        for (int e = t >> 5; e < K3_TE; e += 8) {
            float z1 = (d1_sh[e] - mu) * INV_SIG;
            float z0 = (dt_sh[e] - mu) * INV_SIG;
            in_sh[e * K3_KP + 69 + k] = __expf(-z1*z1) - __expf(-z0*z0);
        }
    }
    __syncthreads();

    // GEMM 128 x 64, K=101.  8 edges x 4 cols per thread, k-blocked by 2.
    const int tn = t & 15, te = t >> 4;
    const int e0 = te * 8, n0 = tn * 4;

    unsigned long long acc[8][2];
    #pragma unroll
    for (int i = 0; i < 8; i++) { acc[i][0] = 0ULL; acc[i][1] = 0ULL; }

    #pragma unroll 5
    for (int kb = 0; kb < 100; kb += 2) {
        float4 b0 = *(const float4*)&W_sh[kb * 64 + n0];
        float4 b1 = *(const float4*)&W_sh[(kb + 1) * 64 + n0];
        float2 ar[8];
        #pragma unroll
        for (int i = 0; i < 8; i++)
            ar[i] = *(const float2*)&in_sh[(e0 + i) * K3_KP + kb];
        unsigned long long b0a = pk2(b0.x, b0.y), b0b = pk2(b0.z, b0.w);
        unsigned long long b1a = pk2(b1.x, b1.y), b1b = pk2(b1.z, b1.w);
        #pragma unroll
        for (int i = 0; i < 8; i++) {
            unsigned long long aa0 = pk2(ar[i].x, ar[i].x);
            acc[i][0] = fma2(aa0, b0a, acc[i][0]);
            acc[i][1] = fma2(aa0, b0b, acc[i][1]);
            unsigned long long aa1 = pk2(ar[i].y, ar[i].y);
            acc[i][0] = fma2(aa1, b1a, acc[i][0]);
            acc[i][1] = fma2(aa1, b1b, acc[i][1]);
        }
    }
    {   // remainder k = 100
        float4 b = *(const float4*)&W_sh[100 * 64 + n0];
        unsigned long long ba = pk2(b.x, b.y), bbq = pk2(b.z, b.w);
        #pragma unroll
        for (int i = 0; i < 8; i++) {
            float a = in_sh[(e0 + i) * K3_KP + 100];
            unsigned long long aa = pk2(a, a);
            acc[i][0] = fma2(aa, ba, acc[i][0]);
            acc[i][1] = fma2(aa, bbq, acc[i][1]);
        }
    }

    float be0 = b_e[n0+0], be1 = b_e[n0+1], be2 = b_e[n0+2], be3 = b_e[n0+3];
    #pragma unroll
    for (int i = 0; i < 8; i++) {
        int e = e0 + i;
        if (e < nvalid) {
            float v0, v1, v2, v3;
            upk2(acc[i][0], v0, v1);
            upk2(acc[i][1], v2, v3);
            float4 o = make_float4(siluf(v0 + be0), siluf(v1 + be1),
                                   siluf(v2 + be2), siluf(v3 + be3));
            int base = (eb + e) * 64 + n0;
            *(float4*)&out[base]            = o;
            *(float4*)&out[base + EH * 64]  = o;
        }
    }
}

// ============================================================================
// launch
// ============================================================================
extern "C" void kernel_launch(void* const* d_in, const int* in_sizes, int n_in,
                              void* d_out, int out_size)
{
    const float *s_t  = (const float*)d_in[0];
    const float *x_t  = (const float*)d_in[1];
    const float *v_t  = (const float*)d_in[2];
    const float *e_t  = (const float*)d_in[3];
    const float *dst_x = (const float*)d_in[4];
    const float *dst_v = (const float*)d_in[5];
    const float *dst_a = (const float*)d_in[6];
    const float *dst_e = (const float*)d_in[7];
    const float *W_x, *b_x, *W_v, *b_v, *W_a, *b_a, *W_n, *b_n, *W_e, *b_e;
    const int *esrc, *edst;

    if (in_sizes[8] == ET) {
        esrc = (const int*)d_in[8];   edst = (const int*)d_in[9];
        W_x = (const float*)d_in[10]; b_x = (const float*)d_in[11];
        W_v = (const float*)d_in[12]; b_v = (const float*)d_in[13];
        W_a = (const float*)d_in[14]; b_a = (const float*)d_in[15];
        W_n = (const float*)d_in[16]; b_n = (const float*)d_in[17];
        W_e = (const float*)d_in[18]; b_e = (const float*)d_in[19];
    } else {
        W_x = (const float*)d_in[8];  b_x = (const float*)d_in[9];
        W_v = (const float*)d_in[10]; b_v = (const float*)d_in[11];
        W_a = (const float*)d_in[12]; b_a = (const float*)d_in[13];
        W_n = (const float*)d_in[14]; b_n = (const float*)d_in[15];
        W_e = (const float*)d_in[16]; b_e = (const float*)d_in[17];
        esrc = (const int*)d_in[18];  edst = (const int*)d_in[19];
    }

    float* out = (float*)d_out;

    const int k1_smem = (64 * 256 + 64 * K1_AP + 256) * (int)sizeof(float);
    const int k3_smem = (K3_TE * K3_KP + EK * 64 + 2 * K3_TE) * (int)sizeof(float);
    cudaFuncSetAttribute(k1_node_h, cudaFuncAttributeMaxDynamicSharedMemorySize, k1_smem);
    cudaFuncSetAttribute(k3_edge,  cudaFuncAttributeMaxDynamicSharedMemorySize, k3_smem);

    k1_node_h<<<(NN + K1_NT - 1) / K1_NT, 256, k1_smem>>>(
        x_t, v_t, dst_x, dst_v, dst_a, W_x, b_x, W_v, b_v, W_a, b_a);

    k2_node_out<<<dim3((NN + K2_BM - 1) / K2_BM, ND / K2_BN), 256>>>(
        s_t, W_n, b_n, out);

    k3_edge<<<(EH + K3_TE - 1) / K3_TE, 256, k3_smem>>>(
        x_t, dst_x, e_t, dst_e, esrc, edst, W_e, b_e, out + NN * ND);
}